// round 15
// baseline (speedup 1.0000x reference)
#include <cuda_runtime.h>
#include <cuda_fp16.h>
#include <cstdint>

typedef uint32_t u32;

// ====================== problem constants ======================
constexpr int T_LEN = 4000;
constexpr int NT    = 413;
constexpr int NE    = 412;
constexpr int OFF   = 206;              // xe[u] = x_ext[u + 206]
constexpr int S_LEN = T_LEN + NT;       // 4413
constexpr int NROWS = 4096;

constexpr int XE_W  = T_LEN + 576;      // 4576
constexpr int MT    = 128;              // GEMM M (rows r)
constexpr int NTT   = 128;              // GEMM N (t positions)
constexpr int N_TTILE = (T_LEN + NTT - 1) / NTT;  // 32
constexpr int N_RBLK  = NROWS / MT;               // 32
constexpr int THREADS = 256;
constexpr int NLIVE  = 8;               // live k-chunks per warp (cc = 0..7)

constexpr float H_SCALE = 512.0f;
constexpr float INV_H_SCALE = 1.0f / 512.0f;

// Warp-private A staging: 32 rows x 64 fp16, pitch 144B, 2-deep ring per warp.
constexpr int PITCHB  = 144;
constexpr int WSTAGE  = 32 * PITCHB;            // 4608
constexpr int BANK_TILES  = 86;
constexpr int BANK_BYTES  = BANK_TILES * 256;   // 22016
constexpr int BANK_HALVES = BANK_TILES * 128;
constexpr int BANK_OFF = 8 * 2 * WSTAGE;        // 73728
constexpr int SMEM_DYN = BANK_OFF + BANK_BYTES; // 95744 -> 2 CTAs/SM

// band: bank tile t nonzero iff t in [14, 67]
constexpr int TLO = 14, THI = 67;

// ====================== device scratch ======================
__device__ __align__(16) __half g_xe[(size_t)NROWS * XE_W];
__device__ __align__(16) __half g_Bd[BANK_HALVES];

// ====================== PTX helpers (family-agnostic, sm_80+) ======================
__device__ __forceinline__ u32 smem_u32(const void* p) {
    u32 a;
    asm("{ .reg .u64 t; cvta.to.shared.u64 t, %1; cvt.u32.u64 %0, t; }" : "=r"(a) : "l"(p));
    return a;
}
#define CP_ASYNC16(dst, src) \
    asm volatile("cp.async.cg.shared.global [%0], [%1], 16;" :: "r"(dst), "l"(src))
#define CP_COMMIT() asm volatile("cp.async.commit_group;" ::: "memory")

#define LDSM4(r, addr) \
    asm volatile("ldmatrix.sync.aligned.m8n8.x4.shared.b16 {%0,%1,%2,%3}, [%4];" \
        : "=r"((r)[0]), "=r"((r)[1]), "=r"((r)[2]), "=r"((r)[3]) : "r"(addr))

#define MMA16816(d, a, b0, b1) \
    asm volatile("mma.sync.aligned.m16n8k16.row.col.f32.f16.f16.f32 " \
        "{%0,%1,%2,%3}, {%4,%5,%6,%7}, {%8,%9}, {%0,%1,%2,%3};" \
        : "+f"((d)[0]), "+f"((d)[1]), "+f"((d)[2]), "+f"((d)[3]) \
        : "r"((a)[0]), "r"((a)[1]), "r"((a)[2]), "r"((a)[3]), \
          "r"(b0), "r"(b1))

// ====================== fused prep kernel (R10, validated) ======================
__device__ __forceinline__ float xext_val(const float* __restrict__ xr, int e) {
    if (e < NE)         return 2.0f * xr[0]         - xr[NE - e];
    if (e < NE + T_LEN) return xr[e - NE];
    return 2.0f * xr[T_LEN - 1] - xr[2 * T_LEN - 2 + NE - e];
}

__global__ void prep_kernel(const float* __restrict__ x, const float* __restrict__ h) {
    const int b = blockIdx.x;
    if (b < NROWS) {
        const float* xr = x + (size_t)b * T_LEN;
        __half* dst = g_xe + (size_t)b * XE_W;
        for (int seg = threadIdx.x; seg < XE_W / 8; seg += blockDim.x) {
            const int u0 = seg * 8;
            __half hv[8];
            #pragma unroll
            for (int q = 0; q < 8; q++) {
                int u = u0 + q;
                float v = (u < S_LEN) ? xext_val(xr, u + OFF) : 0.0f;
                hv[q] = __float2half(v);
            }
            *reinterpret_cast<uint4*>(dst + u0) = *reinterpret_cast<const uint4*>(hv);
        }
    } else {
        int idx = (b - NROWS) * blockDim.x + threadIdx.x;
        if (idx < BANK_HALVES) {
            int t  = idx >> 7;
            int r  = (idx >> 3) & 15;
            int kk = idx & 7;
            int np = r & 7;
            int kp = kk + ((r >= 8) ? 8 : 0);
            int j  = (8 * t - 120) + kp - np;       // hrev index
            float v = (j >= 0 && j < NT) ? h[NT - 1 - j] * H_SCALE : 0.0f;
            g_Bd[idx] = __float2half(v);
        }
    }
}
constexpr int PREP_BANK_BLOCKS = (BANK_HALVES + 255) / 256;   // 43

// ====================== per-live-chunk compute (wn-invariant: B0 = 8cc+8) ======================
// bf ring: pair-index (tile>>1) & 7; cc==0 loads whole window, later ccs load
// only the 4 new pairs (tiles >= B0+6). Identical bank bytes / MMA set as R14.
template<int CC>
__device__ __forceinline__ void compute_chunk(u32 abase, u32 bLane, const u32* aRel,
                                              float (&acc)[2][8][4], u32 (&bf)[8][4]) {
    constexpr int B0 = CC * 8 + 8;                 // 8..64, always live
    #pragma unroll
    for (int p = 0; p < 7; p++) {
        const int tg = B0 + 2 * p;
        const bool inband = (tg + 1 >= TLO) && (tg <= THI);
        const bool isnew  = (CC == 0) || (tg >= B0 + 6);
        if (inband && isnew)
            LDSM4(bf[(tg >> 1) & 7], bLane + (u32)(tg * 256));
    }
    #pragma unroll
    for (int ks = 0; ks < 4; ks++) {
        if (B0 + 2 * ks + 7 >= TLO && B0 + 2 * ks <= THI) {
            u32 a[2][4];
            #pragma unroll
            for (int i = 0; i < 2; i++)
                LDSM4(a[i], abase + aRel[i] + ks * 32);
            #pragma unroll
            for (int i = 0; i < 2; i++)
                #pragma unroll
                for (int j = 0; j < 8; j++) {
                    const int t = B0 + 2 * ks - j + 7;
                    if (t >= TLO && t <= THI) {
                        const int pr = (t >> 1) & 7, sel = (t & 1) * 2;
                        MMA16816(acc[i][j], a[i], bf[pr][sel], bf[pr][sel + 1]);
                    }
                }
        }
    }
}

// ====================== GEMM kernel: warp-private pipeline, barrier-free mainloop ======================
__global__ void __launch_bounds__(THREADS, 2)
fir_gemm_kernel(float* __restrict__ out) {
    extern __shared__ __align__(1024) char smem[];
    const int tid = threadIdx.x;
    const int wid = tid >> 5;
    const int lid = tid & 31;
    const int wm  = wid & 3;        // row slice of 32
    const int wn  = wid >> 2;       // t slice of 64; also k-chunk offset (c = wn + cc)
    const int t0    = blockIdx.x * NTT;
    const int rbase = blockIdx.y * MT;

    const u32 sb    = smem_u32(smem);
    const u32 wbase = sb + wid * (2 * WSTAGE);     // this warp's 2-deep ring
    const u32 bank  = sb + BANK_OFF;

    // ---- warp-private A staging: 8 x 16B per lane per chunk ----
    const char* xebase = (const char*)g_xe;
    u32 asrc[8], adst[8];
    #pragma unroll
    for (int u = 0; u < 8; u++) {
        int idx = u * 32 + lid;           // 0..255
        int r = idx >> 3, seg = idx & 7;  // row 0..31, 16B segment 0..7
        asrc[u] = (u32)(((size_t)(rbase + wm * 32 + r) * XE_W
                         + t0 + wn * 64 + seg * 8) * 2);
        adst[u] = r * PITCHB + seg * 16;
    }
    auto stageW = [&](int cc) {
        const u32 dbase = wbase + (cc & 1) * WSTAGE;
        const int koff = cc * 128;
        #pragma unroll
        for (int u = 0; u < 8; u++)
            CP_ASYNC16(dbase + adst[u], xebase + asrc[u] + koff);
    };

    // ---- prologue: bank (CTA-wide) + first two warp chunks ----
    {
        const char* bdbase = (const char*)g_Bd;
        for (int i = tid; i < BANK_BYTES / 16; i += THREADS)
            CP_ASYNC16(bank + i * 16, bdbase + (size_t)i * 16);
    }
    stageW(0);
    CP_COMMIT();                       // G0: bank part + chunk cc=0
    stageW(1);
    CP_COMMIT();                       // G1: chunk cc=1
    asm volatile("cp.async.wait_group 1;" ::: "memory");   // G0 done
    __syncthreads();                   // bank visible CTA-wide (only barrier)

    // ---- ldmatrix bases (warp-relative) ----
    u32 aRel[2];
    #pragma unroll
    for (int i = 0; i < 2; i++)
        aRel[i] = (i * 16 + (lid & 15)) * PITCHB + ((lid >> 4) * 16);
    const u32 bLane = bank + lid * 16;

    float acc[2][8][4];
    #pragma unroll
    for (int i = 0; i < 2; i++)
        #pragma unroll
        for (int j = 0; j < 8; j++)
            #pragma unroll
            for (int q = 0; q < 4; q++) acc[i][j][q] = 0.0f;

    u32 bf[8][4];     // rolling B-fragment ring

    // ---- barrier-free mainloop: per-warp wait/sync only ----
#define CSTEP(CC)                                                                   \
    do {                                                                            \
        if ((CC) > 0) {                                                             \
            if ((CC) == NLIVE - 1)                                                  \
                asm volatile("cp.async.wait_group 0;" ::: "memory");                \
            else                                                                    \
                asm volatile("cp.async.wait_group 1;" ::: "memory");                \
            __syncwarp();                                                           \
        }                                                                           \
        compute_chunk<(CC)>(wbase + ((CC) & 1) * WSTAGE, bLane, aRel, acc, bf);     \
        if ((CC) + 2 < NLIVE) { stageW((CC) + 2); CP_COMMIT(); }                    \
    } while (0)

    CSTEP(0); CSTEP(1); CSTEP(2); CSTEP(3);
    CSTEP(4); CSTEP(5); CSTEP(6); CSTEP(7);
#undef CSTEP

    // ---- epilogue: D[m=r][n=t] -> out[r*T_LEN + t], undo H_SCALE ----
    #pragma unroll
    for (int i = 0; i < 2; i++) {
        int r0 = rbase + wm * 32 + i * 16 + (lid >> 2);
        #pragma unroll
        for (int j = 0; j < 8; j++) {
            int t = t0 + wn * 64 + j * 8 + 2 * (lid & 3);
            if (t < T_LEN) {
                *reinterpret_cast<float2*>(out + (size_t)r0 * T_LEN + t) =
                    make_float2(acc[i][j][0] * INV_H_SCALE, acc[i][j][1] * INV_H_SCALE);
                *reinterpret_cast<float2*>(out + (size_t)(r0 + 8) * T_LEN + t) =
                    make_float2(acc[i][j][2] * INV_H_SCALE, acc[i][j][3] * INV_H_SCALE);
            }
        }
    }
}

// ====================== launch ======================
extern "C" void kernel_launch(void* const* d_in, const int* in_sizes, int n_in,
                              void* d_out, int out_size)
{
    const float* x = (const float*)d_in[0];   // [64, 64, 4000] f32
    const float* h = (const float*)d_in[1];   // [413] f32
    float* out = (float*)d_out;

    cudaFuncSetAttribute(fir_gemm_kernel,
                         cudaFuncAttributeMaxDynamicSharedMemorySize, SMEM_DYN);

    prep_kernel<<<NROWS + PREP_BANK_BLOCKS, 256>>>(x, h);
    fir_gemm_kernel<<<dim3(N_TTILE, N_RBLK), THREADS, SMEM_DYN>>>(out);
}

// round 16
// speedup vs baseline: 1.0308x; 1.0308x over previous
#include <cuda_runtime.h>
#include <cuda_fp16.h>
#include <cstdint>

typedef uint32_t u32;

// ====================== problem constants ======================
constexpr int T_LEN = 4000;
constexpr int NT    = 413;
constexpr int NE    = 412;
constexpr int OFF   = 206;              // xe[u] = x_ext[u + 206]
constexpr int S_LEN = T_LEN + NT;       // 4413
constexpr int NROWS = 4096;

constexpr int NCHUNK = 9;
constexpr int XE_W  = T_LEN + 576;      // 4576
constexpr int MT    = 128;
constexpr int NTT   = 128;
constexpr int N_TTILE = (T_LEN + NTT - 1) / NTT;  // 32
constexpr int N_RBLK  = NROWS / MT;               // 32
constexpr int THREADS = 256;

constexpr float H_SCALE = 512.0f;
constexpr float INV_H_SCALE = 1.0f / 512.0f;

// A staging: 128 rows x 64 fp16, pitch 144B, 3 stages (R10/R14-validated).
constexpr int PITCHB   = 144;
constexpr int STAGE_A  = 128 * PITCHB;          // 18432
constexpr int NSTAGE   = 3;
constexpr int BANK_TILES  = 86;
constexpr int BANK_BYTES  = BANK_TILES * 256;   // 22016
constexpr int BANK_HALVES = BANK_TILES * 128;
constexpr int SMEM_DYN  = NSTAGE * STAGE_A + BANK_BYTES;   // 77312

// band: bank tile t nonzero iff t in [14, 67]
constexpr int TLO = 14, THI = 67;

// ====================== device scratch ======================
__device__ __align__(16) __half g_xe[(size_t)NROWS * XE_W];
__device__ __align__(16) __half g_Bd[BANK_HALVES];

// ====================== PTX helpers (family-agnostic, sm_80+) ======================
__device__ __forceinline__ u32 smem_u32(const void* p) {
    u32 a;
    asm("{ .reg .u64 t; cvta.to.shared.u64 t, %1; cvt.u32.u64 %0, t; }" : "=r"(a) : "l"(p));
    return a;
}
#define CP_ASYNC16(dst, src) \
    asm volatile("cp.async.cg.shared.global [%0], [%1], 16;" :: "r"(dst), "l"(src))
#define CP_COMMIT() asm volatile("cp.async.commit_group;" ::: "memory")

#define LDSM4(r, addr) \
    asm volatile("ldmatrix.sync.aligned.m8n8.x4.shared.b16 {%0,%1,%2,%3}, [%4];" \
        : "=r"((r)[0]), "=r"((r)[1]), "=r"((r)[2]), "=r"((r)[3]) : "r"(addr))

#define MMA16816(d, a, b0, b1) \
    asm volatile("mma.sync.aligned.m16n8k16.row.col.f32.f16.f16.f32 " \
        "{%0,%1,%2,%3}, {%4,%5,%6,%7}, {%8,%9}, {%0,%1,%2,%3};" \
        : "+f"((d)[0]), "+f"((d)[1]), "+f"((d)[2]), "+f"((d)[3]) \
        : "r"((a)[0]), "r"((a)[1]), "r"((a)[2]), "r"((a)[3]), \
          "r"(b0), "r"(b1))

// ====================== fused prep kernel (validated) ======================
__device__ __forceinline__ float xext_val(const float* __restrict__ xr, int e) {
    if (e < NE)         return 2.0f * xr[0]         - xr[NE - e];
    if (e < NE + T_LEN) return xr[e - NE];
    return 2.0f * xr[T_LEN - 1] - xr[2 * T_LEN - 2 + NE - e];
}

__global__ void prep_kernel(const float* __restrict__ x, const float* __restrict__ h) {
    const int b = blockIdx.x;
    if (b < NROWS) {
        const float* xr = x + (size_t)b * T_LEN;
        __half* dst = g_xe + (size_t)b * XE_W;
        for (int seg = threadIdx.x; seg < XE_W / 8; seg += blockDim.x) {
            const int u0 = seg * 8;
            __half hv[8];
            #pragma unroll
            for (int q = 0; q < 8; q++) {
                int u = u0 + q;
                float v = (u < S_LEN) ? xext_val(xr, u + OFF) : 0.0f;
                hv[q] = __float2half(v);
            }
            *reinterpret_cast<uint4*>(dst + u0) = *reinterpret_cast<const uint4*>(hv);
        }
    } else {
        int idx = (b - NROWS) * blockDim.x + threadIdx.x;
        if (idx < BANK_HALVES) {
            int t  = idx >> 7;
            int r  = (idx >> 3) & 15;
            int kk = idx & 7;
            int np = r & 7;
            int kp = kk + ((r >= 8) ? 8 : 0);
            int j  = (8 * t - 120) + kp - np;       // hrev index
            float v = (j >= 0 && j < NT) ? h[NT - 1 - j] * H_SCALE : 0.0f;
            g_Bd[idx] = __float2half(v);
        }
    }
}
constexpr int PREP_BANK_BLOCKS = (BANK_HALVES + 255) / 256;   // 43

// ====================== interleaved chunk body ======================
// Pair P covers bank tiles (B0+2P, B0+2P+1); ks block uses pairs P = ks..ks+3.
template<int B0, int P>
__device__ __forceinline__ void ldB(u32 bLane, u32 (&bf)[7][4]) {
    constexpr int tg = B0 + 2 * P;
    if constexpr (tg + 1 >= TLO && tg <= THI)
        LDSM4(bf[P], bLane + (u32)(tg * 256));
}
template<int B0, int KS>
__device__ __forceinline__ void ldA(u32 abase, const u32* aRel, u32 (&ab)[2][4]) {
    if constexpr (B0 + 2 * KS + 7 >= TLO && B0 + 2 * KS <= THI) {
        LDSM4(ab[0], abase + aRel[0] + KS * 32);
        LDSM4(ab[1], abase + aRel[1] + KS * 32);
    }
}
template<int B0, int KS, int I>
__device__ __forceinline__ void mmaHalf(const u32 (&a)[4], const u32 (&bf)[7][4],
                                        float (&acc)[2][8][4]) {
    if constexpr (B0 + 2 * KS + 7 >= TLO && B0 + 2 * KS <= THI) {
        #pragma unroll
        for (int jj = 0; jj < 8; jj++) {
            const int j = 7 - jj;                  // t ascending: newest pair last
            const int t = B0 + 2 * KS + 7 - j;
            if (t >= TLO && t <= THI) {
                const int P   = (2 * KS + 7 - j) >> 1;
                const int sel = ((2 * KS + 7 - j) & 1) * 2;
                MMA16816(acc[I][j], a, bf[P][sel], bf[P][sel + 1]);
            }
        }
    }
}

// Hand-scheduled: small head burst (4 B-pairs + A(ks0)), then LDSMs woven
// between MMA half-blocks. Same guard set as R14 -> bit-identical output.
template<int C, int WN>
__device__ __forceinline__ void compute_chunk(u32 abase, u32 bLane, const u32* aRel,
                                              float (&acc)[2][8][4]) {
    constexpr int B0 = (C - WN) * 8 + 8;
    if constexpr (B0 + 13 < TLO || B0 > THI) return;

    u32 bf[7][4];
    u32 a[2][2][4];

    ldB<B0, 0>(bLane, bf);
    ldB<B0, 1>(bLane, bf);
    ldB<B0, 2>(bLane, bf);
    ldB<B0, 3>(bLane, bf);
    ldA<B0, 0>(abase, aRel, a[0]);

    mmaHalf<B0, 0, 0>(a[0][0], bf, acc);
    ldB<B0, 4>(bLane, bf);
    mmaHalf<B0, 0, 1>(a[0][1], bf, acc);
    ldA<B0, 1>(abase, aRel, a[1]);

    mmaHalf<B0, 1, 0>(a[1][0], bf, acc);
    ldB<B0, 5>(bLane, bf);
    mmaHalf<B0, 1, 1>(a[1][1], bf, acc);
    ldA<B0, 2>(abase, aRel, a[0]);

    mmaHalf<B0, 2, 0>(a[0][0], bf, acc);
    ldB<B0, 6>(bLane, bf);
    mmaHalf<B0, 2, 1>(a[0][1], bf, acc);
    ldA<B0, 3>(abase, aRel, a[1]);

    mmaHalf<B0, 3, 0>(a[1][0], bf, acc);
    mmaHalf<B0, 3, 1>(a[1][1], bf, acc);
}

// ====================== GEMM kernel (R14 pipeline) ======================
__global__ void __launch_bounds__(THREADS, 2)
fir_gemm_kernel(float* __restrict__ out) {
    extern __shared__ __align__(1024) char smem[];
    const int tid = threadIdx.x;
    const int wid = tid >> 5;
    const int lid = tid & 31;
    const int wm  = wid & 3;        // row slice of 32
    const int wn  = wid >> 2;       // t slice of 64
    const int t0    = blockIdx.x * NTT;
    const int rbase = blockIdx.y * MT;

    const u32 sb   = smem_u32(smem);
    const u32 bank = sb + NSTAGE * STAGE_A;

    // ---- A staging addresses (4 x 16B per thread per chunk) ----
    const char* xebase = (const char*)g_xe;
    u32 asrc[4], adst[4];
    #pragma unroll
    for (int it = 0; it < 4; it++) {
        int idx = it * THREADS + tid;   // 0..1023
        int r = idx >> 3, seg = idx & 7;
        asrc[it] = (u32)(((size_t)(rbase + r) * XE_W + t0 + seg * 8) * 2);
        adst[it] = r * PITCHB + seg * 16;
    }
    auto stageA = [&](int c, u32 dbase) {
        const int koff = c * 128;
        #pragma unroll
        for (int it = 0; it < 4; it++)
            CP_ASYNC16(dbase + adst[it], xebase + asrc[it] + koff);
    };

    // ---- one-time bank load + first two A stages ----
    {
        const char* bdbase = (const char*)g_Bd;
        for (int i = tid; i < BANK_BYTES / 16; i += THREADS)
            CP_ASYNC16(bank + i * 16, bdbase + (size_t)i * 16);
    }
    stageA(0, sb);
    CP_COMMIT();                          // group: bank + chunk0
    stageA(1, sb + STAGE_A);
    CP_COMMIT();                          // group: chunk1

    // ---- ldmatrix bases ----
    u32 aRel[2];
    #pragma unroll
    for (int i = 0; i < 2; i++)
        aRel[i] = (wm * 32 + i * 16 + (lid & 15)) * PITCHB + ((lid >> 4) * 16);
    const u32 bLane = bank + lid * 16;

    float acc[2][8][4];
    #pragma unroll
    for (int i = 0; i < 2; i++)
        #pragma unroll
        for (int j = 0; j < 8; j++)
            #pragma unroll
            for (int q = 0; q < 4; q++) acc[i][j][q] = 0.0f;

#define GSTEP(C)                                                                         \
    do {                                                                                 \
        if ((C) == NCHUNK - 1) asm volatile("cp.async.wait_group 0;" ::: "memory");      \
        else                   asm volatile("cp.async.wait_group 1;" ::: "memory");      \
        __syncthreads();                                                                 \
        if ((C) + 2 < NCHUNK) {                                                          \
            stageA((C) + 2, sb + (((C) + 2) % NSTAGE) * STAGE_A);                        \
            CP_COMMIT();                                                                 \
        }                                                                                \
        const u32 abase_ = sb + ((C) % NSTAGE) * STAGE_A;                                \
        if (wn == 0) compute_chunk<(C), 0>(abase_, bLane, aRel, acc);                    \
        else         compute_chunk<(C), 1>(abase_, bLane, aRel, acc);                    \
    } while (0)

    GSTEP(0); GSTEP(1); GSTEP(2); GSTEP(3); GSTEP(4);
    GSTEP(5); GSTEP(6); GSTEP(7); GSTEP(8);
#undef GSTEP

    // ---- epilogue: D[m=r][n=t] -> out[r*T_LEN + t], undo H_SCALE ----
    #pragma unroll
    for (int i = 0; i < 2; i++) {
        int r0 = rbase + wm * 32 + i * 16 + (lid >> 2);
        #pragma unroll
        for (int j = 0; j < 8; j++) {
            int t = t0 + wn * 64 + j * 8 + 2 * (lid & 3);
            if (t < T_LEN) {
                *reinterpret_cast<float2*>(out + (size_t)r0 * T_LEN + t) =
                    make_float2(acc[i][j][0] * INV_H_SCALE, acc[i][j][1] * INV_H_SCALE);
                *reinterpret_cast<float2*>(out + (size_t)(r0 + 8) * T_LEN + t) =
                    make_float2(acc[i][j][2] * INV_H_SCALE, acc[i][j][3] * INV_H_SCALE);
            }
        }
    }
}

// ====================== launch ======================
extern "C" void kernel_launch(void* const* d_in, const int* in_sizes, int n_in,
                              void* d_out, int out_size)
{
    const float* x = (const float*)d_in[0];   // [64, 64, 4000] f32
    const float* h = (const float*)d_in[1];   // [413] f32
    float* out = (float*)d_out;

    cudaFuncSetAttribute(fir_gemm_kernel,
                         cudaFuncAttributeMaxDynamicSharedMemorySize, SMEM_DYN);

    prep_kernel<<<NROWS + PREP_BANK_BLOCKS, 256>>>(x, h);
    fir_gemm_kernel<<<dim3(N_TTILE, N_RBLK), THREADS, SMEM_DYN>>>(out);
}

// round 17
// speedup vs baseline: 1.0542x; 1.0227x over previous
#include <cuda_runtime.h>
#include <cuda_fp16.h>
#include <cstdint>

typedef uint32_t u32;

// ====================== problem constants ======================
constexpr int T_LEN = 4000;
constexpr int NT    = 413;
constexpr int NE    = 412;
constexpr int OFF   = 206;              // xe[u] = x_ext[u + 206]
constexpr int S_LEN = T_LEN + NT;       // 4413
constexpr int NROWS = 4096;

constexpr int NCHUNK = 9;
constexpr int XE_W  = T_LEN + 576;      // 4576
constexpr int MT    = 64;               // rows per CTA (halved)
constexpr int NTT   = 128;              // t per CTA
constexpr int N_TTILE = (T_LEN + NTT - 1) / NTT;  // 32
constexpr int N_RBLK  = NROWS / MT;               // 64
constexpr int THREADS = 256;

constexpr float H_SCALE = 512.0f;
constexpr float INV_H_SCALE = 1.0f / 512.0f;

// A staging: 64 rows x 64 fp16, pitch 144B, 3 stages.
constexpr int PITCHB   = 144;
constexpr int STAGE_A  = 64 * PITCHB;           // 9216
constexpr int NSTAGE   = 3;
constexpr int BANK_TILES  = 86;
constexpr int BANK_BYTES  = BANK_TILES * 256;   // 22016
constexpr int BANK_HALVES = BANK_TILES * 128;
constexpr int SMEM_DYN  = NSTAGE * STAGE_A + BANK_BYTES;   // 49664 -> 3 CTAs/SM

// band: bank tile t nonzero iff t in [14, 67]
constexpr int TLO = 14, THI = 67;

// ====================== device scratch ======================
__device__ __align__(16) __half g_xe[(size_t)NROWS * XE_W];
__device__ __align__(16) __half g_Bd[BANK_HALVES];

// ====================== PTX helpers (family-agnostic, sm_80+) ======================
__device__ __forceinline__ u32 smem_u32(const void* p) {
    u32 a;
    asm("{ .reg .u64 t; cvta.to.shared.u64 t, %1; cvt.u32.u64 %0, t; }" : "=r"(a) : "l"(p));
    return a;
}
#define CP_ASYNC16(dst, src) \
    asm volatile("cp.async.cg.shared.global [%0], [%1], 16;" :: "r"(dst), "l"(src))
#define CP_COMMIT() asm volatile("cp.async.commit_group;" ::: "memory")

#define LDSM4(r, addr) \
    asm volatile("ldmatrix.sync.aligned.m8n8.x4.shared.b16 {%0,%1,%2,%3}, [%4];" \
        : "=r"((r)[0]), "=r"((r)[1]), "=r"((r)[2]), "=r"((r)[3]) : "r"(addr))

#define MMA16816(d, a, b0, b1) \
    asm volatile("mma.sync.aligned.m16n8k16.row.col.f32.f16.f16.f32 " \
        "{%0,%1,%2,%3}, {%4,%5,%6,%7}, {%8,%9}, {%0,%1,%2,%3};" \
        : "+f"((d)[0]), "+f"((d)[1]), "+f"((d)[2]), "+f"((d)[3]) \
        : "r"((a)[0]), "r"((a)[1]), "r"((a)[2]), "r"((a)[3]), \
          "r"(b0), "r"(b1))

// ====================== fused prep kernel (validated) ======================
__device__ __forceinline__ float xext_val(const float* __restrict__ xr, int e) {
    if (e < NE)         return 2.0f * xr[0]         - xr[NE - e];
    if (e < NE + T_LEN) return xr[e - NE];
    return 2.0f * xr[T_LEN - 1] - xr[2 * T_LEN - 2 + NE - e];
}

__global__ void prep_kernel(const float* __restrict__ x, const float* __restrict__ h) {
    const int b = blockIdx.x;
    if (b < NROWS) {
        const float* xr = x + (size_t)b * T_LEN;
        __half* dst = g_xe + (size_t)b * XE_W;
        for (int seg = threadIdx.x; seg < XE_W / 8; seg += blockDim.x) {
            const int u0 = seg * 8;
            __half hv[8];
            #pragma unroll
            for (int q = 0; q < 8; q++) {
                int u = u0 + q;
                float v = (u < S_LEN) ? xext_val(xr, u + OFF) : 0.0f;
                hv[q] = __float2half(v);
            }
            *reinterpret_cast<uint4*>(dst + u0) = *reinterpret_cast<const uint4*>(hv);
        }
    } else {
        int idx = (b - NROWS) * blockDim.x + threadIdx.x;
        if (idx < BANK_HALVES) {
            int t  = idx >> 7;
            int r  = (idx >> 3) & 15;
            int kk = idx & 7;
            int np = r & 7;
            int kp = kk + ((r >= 8) ? 8 : 0);
            int j  = (8 * t - 120) + kp - np;       // hrev index
            float v = (j >= 0 && j < NT) ? h[NT - 1 - j] * H_SCALE : 0.0f;
            g_Bd[idx] = __float2half(v);
        }
    }
}
constexpr int PREP_BANK_BLOCKS = (BANK_HALVES + 255) / 256;   // 43

// ====================== interleaved chunk body (single m-tile) ======================
template<int B0, int P>
__device__ __forceinline__ void ldB(u32 bLane, u32 (&bf)[7][4]) {
    constexpr int tg = B0 + 2 * P;
    if constexpr (tg + 1 >= TLO && tg <= THI)
        LDSM4(bf[P], bLane + (u32)(tg * 256));
}
template<int B0, int KS>
__device__ __forceinline__ void ldA(u32 abase, u32 aRel, u32 (&ab)[4]) {
    if constexpr (B0 + 2 * KS + 7 >= TLO && B0 + 2 * KS <= THI)
        LDSM4(ab, abase + aRel + KS * 32);
}
// Quad H of ks block: H=0 -> j=7..4 (t = B0+2KS..+3), H=1 -> j=3..0 (t = +4..+7)
template<int B0, int KS, int H>
__device__ __forceinline__ void mmaQuad(const u32 (&a)[4], const u32 (&bf)[7][4],
                                        float (&acc)[8][4]) {
    if constexpr (B0 + 2 * KS + 7 >= TLO && B0 + 2 * KS <= THI) {
        #pragma unroll
        for (int jj = 4 * H; jj < 4 * H + 4; jj++) {
            const int j = 7 - jj;
            const int t = B0 + 2 * KS + 7 - j;
            if (t >= TLO && t <= THI) {
                const int P   = (2 * KS + 7 - j) >> 1;
                const int sel = ((2 * KS + 7 - j) & 1) * 2;
                MMA16816(acc[j], a, bf[P][sel], bf[P][sel + 1]);
            }
        }
    }
}

template<int C, int WN>
__device__ __forceinline__ void compute_chunk(u32 abase, u32 bLane, u32 aRel,
                                              float (&acc)[8][4]) {
    constexpr int B0 = (C - WN) * 8 + 8;
    if constexpr (B0 + 13 < TLO || B0 > THI) return;

    u32 bf[7][4];
    u32 a0[4], a1[4];

    ldB<B0, 0>(bLane, bf);
    ldB<B0, 1>(bLane, bf);
    ldB<B0, 2>(bLane, bf);
    ldB<B0, 3>(bLane, bf);
    ldA<B0, 0>(abase, aRel, a0);

    mmaQuad<B0, 0, 0>(a0, bf, acc);
    ldB<B0, 4>(bLane, bf);
    mmaQuad<B0, 0, 1>(a0, bf, acc);
    ldA<B0, 1>(abase, aRel, a1);

    mmaQuad<B0, 1, 0>(a1, bf, acc);
    ldB<B0, 5>(bLane, bf);
    mmaQuad<B0, 1, 1>(a1, bf, acc);
    ldA<B0, 2>(abase, aRel, a0);

    mmaQuad<B0, 2, 0>(a0, bf, acc);
    ldB<B0, 6>(bLane, bf);
    mmaQuad<B0, 2, 1>(a0, bf, acc);
    ldA<B0, 3>(abase, aRel, a1);

    mmaQuad<B0, 3, 0>(a1, bf, acc);
    mmaQuad<B0, 3, 1>(a1, bf, acc);
}

// ====================== GEMM kernel (3 CTAs/SM) ======================
__global__ void __launch_bounds__(THREADS, 3)
fir_gemm_kernel(float* __restrict__ out) {
    extern __shared__ __align__(1024) char smem[];
    const int tid = threadIdx.x;
    const int wid = tid >> 5;
    const int lid = tid & 31;
    const int wm  = wid & 3;        // row slice of 16
    const int wn  = wid >> 2;       // t slice of 64
    const int t0    = blockIdx.x * NTT;
    const int rbase = blockIdx.y * MT;

    const u32 sb   = smem_u32(smem);
    const u32 bank = sb + NSTAGE * STAGE_A;

    // ---- A staging addresses (2 x 16B per thread per chunk) ----
    const char* xebase = (const char*)g_xe;
    u32 asrc[2], adst[2];
    #pragma unroll
    for (int it = 0; it < 2; it++) {
        int idx = it * THREADS + tid;   // 0..511
        int r = idx >> 3, seg = idx & 7;
        asrc[it] = (u32)(((size_t)(rbase + r) * XE_W + t0 + seg * 8) * 2);
        adst[it] = r * PITCHB + seg * 16;
    }
    auto stageA = [&](int c, u32 dbase) {
        const int koff = c * 128;
        #pragma unroll
        for (int it = 0; it < 2; it++)
            CP_ASYNC16(dbase + adst[it], xebase + asrc[it] + koff);
    };

    // ---- one-time bank load + first two A stages ----
    {
        const char* bdbase = (const char*)g_Bd;
        for (int i = tid; i < BANK_BYTES / 16; i += THREADS)
            CP_ASYNC16(bank + i * 16, bdbase + (size_t)i * 16);
    }
    stageA(0, sb);
    CP_COMMIT();                          // group: bank + chunk0
    stageA(1, sb + STAGE_A);
    CP_COMMIT();                          // group: chunk1

    // ---- ldmatrix bases ----
    const u32 aRel = (wm * 16 + (lid & 15)) * PITCHB + ((lid >> 4) * 16);
    const u32 bLane = bank + lid * 16;

    float acc[8][4];
    #pragma unroll
    for (int j = 0; j < 8; j++)
        #pragma unroll
        for (int q = 0; q < 4; q++) acc[j][q] = 0.0f;

#define GSTEP(C)                                                                         \
    do {                                                                                 \
        if ((C) == NCHUNK - 1) asm volatile("cp.async.wait_group 0;" ::: "memory");      \
        else                   asm volatile("cp.async.wait_group 1;" ::: "memory");      \
        __syncthreads();                                                                 \
        if ((C) + 2 < NCHUNK) {                                                          \
            stageA((C) + 2, sb + (((C) + 2) % NSTAGE) * STAGE_A);                        \
            CP_COMMIT();                                                                 \
        }                                                                                \
        const u32 abase_ = sb + ((C) % NSTAGE) * STAGE_A;                                \
        if (wn == 0) compute_chunk<(C), 0>(abase_, bLane, aRel, acc);                    \
        else         compute_chunk<(C), 1>(abase_, bLane, aRel, acc);                    \
    } while (0)

    GSTEP(0); GSTEP(1); GSTEP(2); GSTEP(3); GSTEP(4);
    GSTEP(5); GSTEP(6); GSTEP(7); GSTEP(8);
#undef GSTEP

    // ---- epilogue: D[m=r][n=t] -> out[r*T_LEN + t], undo H_SCALE ----
    {
        int r0 = rbase + wm * 16 + (lid >> 2);
        #pragma unroll
        for (int j = 0; j < 8; j++) {
            int t = t0 + wn * 64 + j * 8 + 2 * (lid & 3);
            if (t < T_LEN) {
                *reinterpret_cast<float2*>(out + (size_t)r0 * T_LEN + t) =
                    make_float2(acc[j][0] * INV_H_SCALE, acc[j][1] * INV_H_SCALE);
                *reinterpret_cast<float2*>(out + (size_t)(r0 + 8) * T_LEN + t) =
                    make_float2(acc[j][2] * INV_H_SCALE, acc[j][3] * INV_H_SCALE);
            }
        }
    }
}

// ====================== launch ======================
extern "C" void kernel_launch(void* const* d_in, const int* in_sizes, int n_in,
                              void* d_out, int out_size)
{
    const float* x = (const float*)d_in[0];   // [64, 64, 4000] f32
    const float* h = (const float*)d_in[1];   // [413] f32
    float* out = (float*)d_out;

    cudaFuncSetAttribute(fir_gemm_kernel,
                         cudaFuncAttributeMaxDynamicSharedMemorySize, SMEM_DYN);

    prep_kernel<<<NROWS + PREP_BANK_BLOCKS, 256>>>(x, h);
    fir_gemm_kernel<<<dim3(N_TTILE, N_RBLK), THREADS, SMEM_DYN>>>(out);
}